// round 13
// baseline (speedup 1.0000x reference)
#include <cuda_runtime.h>
#include <mma.h>
#include <math.h>

using namespace nvcuda;

#define NMAX 50000
#define EMAX 800000

// ---------------- scratch (no allocation allowed) ----------------
__device__ __align__(16) int   g_cnt[NMAX];        // in-degree (counting-sort hist)
__device__ __align__(16) int   g_rp[NMAX];         // CSR row ptr; fill advances it to row END
__device__ int                 g_base;             // global edge counter for block bases
__device__ __align__(16) float g_dinv[NMAX];
__device__ __align__(16) float g_Wt[128 * 64];     // tf32, transformed W1: Wt[d*64 + k*16+f]
__device__ __align__(16) float g_xs[(NMAX + 64) * 128]; // tf32(x*invrs), padded rows read 0
__device__ __align__(16) float2 g_csr[EMAX];       // (src bits, weight)
__device__ __align__(16) float g_y[4 * NMAX * 16]; // layer-1 projections y_k
__device__ __align__(16) float g_t[NMAX * 16];
__device__ __align__(16) float g_u[NMAX * 16];
__device__ __align__(16) float g_G[4 * NMAX * 16]; // layer-2 hops

// ---------------- CSR build ----------------
__global__ void k_zero1(int* __restrict__ a, int* __restrict__ base, int n) {
  int i = blockIdx.x * blockDim.x + threadIdx.x;
  if (i < n) a[i] = 0;
  if (i == 0) *base = 0;
}

__global__ void k_hist(const int* __restrict__ ei, int* __restrict__ cnt, int E) {
  int e = (blockIdx.x * blockDim.x + threadIdx.x) * 2;
  if (e >= E) return;
  atomicAdd(&cnt[ei[E + e]], 1);
  if (e + 1 < E) atomicAdd(&cnt[ei[E + e + 1]], 1);
}

// warp per row: xs[r] = tf32(x[r] / max(rowsum, 1e-8))
__global__ void k_prepX(const float* __restrict__ x, float* __restrict__ xs, int n) {
  int w = (blockIdx.x * blockDim.x + threadIdx.x) >> 5;
  int lane = threadIdx.x & 31;
  if (w >= n) return;
  const float4* x4 = (const float4*)x;
  float4 v = x4[w * 32 + lane];
  float s = v.x + v.y + v.z + v.w;
  #pragma unroll
  for (int o = 16; o; o >>= 1) s += __shfl_xor_sync(0xffffffffu, s, o);
  float sc = 1.0f / fmaxf(s, 1e-8f);
  float4 ov = make_float4(wmma::__float_to_tf32(v.x * sc), wmma::__float_to_tf32(v.y * sc),
                          wmma::__float_to_tf32(v.z * sc), wmma::__float_to_tf32(v.w * sc));
  ((float4*)xs)[w * 32 + lane] = ov;
}

// one-time W1 transform: Wt[d*64 + k*16+f] = tf32(W1[(k*128+d)*16+f])
__global__ void k_prepW(const float* __restrict__ W1, float* __restrict__ Wt) {
  int tid = threadIdx.x;
  for (int s = tid; s < 8192; s += 256) {
    int d = s >> 6, c = s & 63;
    Wt[s] = wmma::__float_to_tf32(W1[(((c >> 4) << 7) | d) * 16 + (c & 15)]);
  }
}

// per-1024-block exclusive scan (warp shuffles) + atomic block base -> FINAL rp.
__global__ __launch_bounds__(1024) void k_scan1(const int* __restrict__ cnt,
                                                int* __restrict__ rp,
                                                int* __restrict__ base,
                                                float* __restrict__ dinv, int n) {
  __shared__ int ws[32];
  __shared__ int blockBase;
  int t = threadIdx.x;
  int i = blockIdx.x * 1024 + t;
  int c = (i < n) ? cnt[i] : 0;
  if (i < n) dinv[i] = (c > 0) ? rsqrtf((float)c) : 0.f;
  int s = c;
  #pragma unroll
  for (int o = 1; o < 32; o <<= 1) {
    int p = __shfl_up_sync(0xffffffffu, s, o);
    if ((t & 31) >= o) s += p;
  }
  if ((t & 31) == 31) ws[t >> 5] = s;
  __syncthreads();
  if (t < 32) {
    int b = ws[t];
    int sb = b;
    #pragma unroll
    for (int o = 1; o < 32; o <<= 1) {
      int p = __shfl_up_sync(0xffffffffu, sb, o);
      if (t >= o) sb += p;
    }
    ws[t] = sb - b;
    if (t == 31) blockBase = atomicAdd(base, sb);
  }
  __syncthreads();
  if (i < n) rp[i] = blockBase + (s - c) + ws[t >> 5];
}

// fill CSR entries: (src, dinv[src]*dinv[dst]) into dst buckets. 2 edges/thread.
__global__ void k_fill(const int* __restrict__ ei, const float* __restrict__ dinv,
                       int* __restrict__ rp, float2* __restrict__ csr, int E) {
  int e = (blockIdx.x * blockDim.x + threadIdx.x) * 2;
  if (e >= E) return;
  int s0 = ei[e];
  int d0 = ei[E + e];
  float w0 = dinv[s0] * dinv[d0];
  int p0 = atomicAdd(&rp[d0], 1);
  if (e + 1 < E) {
    int s1 = ei[e + 1];
    int d1 = ei[E + e + 1];
    float w1 = dinv[s1] * dinv[d1];
    int p1 = atomicAdd(&rp[d1], 1);
    csr[p0] = make_float2(__int_as_float(s0), w0);
    csr[p1] = make_float2(__int_as_float(s1), w1);
  } else {
    csr[p0] = make_float2(__int_as_float(s0), w0);
  }
}

// ---------------- gather SpMM: out[r] = epi(init[r] + sum_e w_e * in[src_e]) ----------------
// 4 threads per row, 8-wide unrolled edge loop.
__global__ __launch_bounds__(256) void k_spmm(
    const int* __restrict__ rp, const int* __restrict__ cnt,
    const float2* __restrict__ csr, const float4* __restrict__ in,
    const float4* __restrict__ init, const float* __restrict__ bias,
    float4* __restrict__ out, int n) {
  int idx = blockIdx.x * blockDim.x + threadIdx.x;
  int r = idx >> 2;
  if (r >= n) return;
  int q = idx & 3;
  int len = __ldg(&cnt[r]);
  int start = __ldg(&rp[r]) - len;
  float4 a0 = make_float4(0.f, 0.f, 0.f, 0.f);
  float4 a1 = make_float4(0.f, 0.f, 0.f, 0.f);
  if (init) a0 = init[(r << 2) + q];
  int i = 0;
  for (; i + 8 <= len; i += 8) {
    float2 e0 = __ldg(&csr[start + i + 0]);
    float2 e1 = __ldg(&csr[start + i + 1]);
    float2 e2 = __ldg(&csr[start + i + 2]);
    float2 e3 = __ldg(&csr[start + i + 3]);
    float2 e4 = __ldg(&csr[start + i + 4]);
    float2 e5 = __ldg(&csr[start + i + 5]);
    float2 e6 = __ldg(&csr[start + i + 6]);
    float2 e7 = __ldg(&csr[start + i + 7]);
    float4 v0 = __ldg(&in[(__float_as_int(e0.x) << 2) + q]);
    float4 v1 = __ldg(&in[(__float_as_int(e1.x) << 2) + q]);
    float4 v2 = __ldg(&in[(__float_as_int(e2.x) << 2) + q]);
    float4 v3 = __ldg(&in[(__float_as_int(e3.x) << 2) + q]);
    float4 v4 = __ldg(&in[(__float_as_int(e4.x) << 2) + q]);
    float4 v5 = __ldg(&in[(__float_as_int(e5.x) << 2) + q]);
    float4 v6 = __ldg(&in[(__float_as_int(e6.x) << 2) + q]);
    float4 v7 = __ldg(&in[(__float_as_int(e7.x) << 2) + q]);
    a0.x += e0.y * v0.x; a0.y += e0.y * v0.y; a0.z += e0.y * v0.z; a0.w += e0.y * v0.w;
    a1.x += e1.y * v1.x; a1.y += e1.y * v1.y; a1.z += e1.y * v1.z; a1.w += e1.y * v1.w;
    a0.x += e2.y * v2.x; a0.y += e2.y * v2.y; a0.z += e2.y * v2.z; a0.w += e2.y * v2.w;
    a1.x += e3.y * v3.x; a1.y += e3.y * v3.y; a1.z += e3.y * v3.z; a1.w += e3.y * v3.w;
    a0.x += e4.y * v4.x; a0.y += e4.y * v4.y; a0.z += e4.y * v4.z; a0.w += e4.y * v4.w;
    a1.x += e5.y * v5.x; a1.y += e5.y * v5.y; a1.z += e5.y * v5.z; a1.w += e5.y * v5.w;
    a0.x += e6.y * v6.x; a0.y += e6.y * v6.y; a0.z += e6.y * v6.z; a0.w += e6.y * v6.w;
    a1.x += e7.y * v7.x; a1.y += e7.y * v7.y; a1.z += e7.y * v7.z; a1.w += e7.y * v7.w;
  }
  for (; i + 4 <= len; i += 4) {
    float2 e0 = __ldg(&csr[start + i + 0]);
    float2 e1 = __ldg(&csr[start + i + 1]);
    float2 e2 = __ldg(&csr[start + i + 2]);
    float2 e3 = __ldg(&csr[start + i + 3]);
    float4 v0 = __ldg(&in[(__float_as_int(e0.x) << 2) + q]);
    float4 v1 = __ldg(&in[(__float_as_int(e1.x) << 2) + q]);
    float4 v2 = __ldg(&in[(__float_as_int(e2.x) << 2) + q]);
    float4 v3 = __ldg(&in[(__float_as_int(e3.x) << 2) + q]);
    a0.x += e0.y * v0.x; a0.y += e0.y * v0.y; a0.z += e0.y * v0.z; a0.w += e0.y * v0.w;
    a1.x += e1.y * v1.x; a1.y += e1.y * v1.y; a1.z += e1.y * v1.z; a1.w += e1.y * v1.w;
    a0.x += e2.y * v2.x; a0.y += e2.y * v2.y; a0.z += e2.y * v2.z; a0.w += e2.y * v2.w;
    a1.x += e3.y * v3.x; a1.y += e3.y * v3.y; a1.z += e3.y * v3.z; a1.w += e3.y * v3.w;
  }
  for (; i < len; i++) {
    float2 e0 = __ldg(&csr[start + i]);
    float4 v0 = __ldg(&in[(__float_as_int(e0.x) << 2) + q]);
    a0.x += e0.y * v0.x; a0.y += e0.y * v0.y; a0.z += e0.y * v0.z; a0.w += e0.y * v0.w;
  }
  float4 acc = make_float4(a0.x + a1.x, a0.y + a1.y, a0.z + a1.z, a0.w + a1.w);
  if (bias) {
    float4 bb = ((const float4*)bias)[q];
    acc = make_float4(fmaxf(acc.x + bb.x, 0.f), fmaxf(acc.y + bb.y, 0.f),
                      fmaxf(acc.z + bb.z, 0.f), fmaxf(acc.w + bb.w, 0.f));
  }
  out[(r << 2) + q] = acc;
}

// ---------------- GEMM1 (tf32 WMMA v4): y[k][n][16] = xs @ W1[k] ----------------
// A-fragments loaded DIRECTLY from gmem xs (pre-scaled, pre-tf32, padded rows).
// Zero X smem, one barrier. 256 thr = 8 warps: 4 row-groups x 2 col-halves.
__global__ __launch_bounds__(256) void k_gemm1(
    const float* __restrict__ xs, const float* __restrict__ Wt,
    float* __restrict__ y, int n) {
  __shared__ float Ws[128][68];   // tf32 W, padded stride
  int tid = threadIdx.x;
  int wid = tid >> 5;
  int rg = wid >> 1;
  int cg = wid & 1;
  int rowBase = blockIdx.x * 64;

  const float4* Wt4 = (const float4*)Wt;
  for (int s = tid; s < 2048; s += 256) {
    int d = s >> 4, c4 = s & 15;
    *(float4*)&Ws[d][c4 << 2] = Wt4[s];
  }

  wmma::fragment<wmma::accumulator, 16, 16, 8, float> acc[2];
  wmma::fill_fragment(acc[0], 0.0f);
  wmma::fill_fragment(acc[1], 0.0f);
  __syncthreads();

  const float* arow = xs + (rowBase + (rg << 4)) * 128;
  #pragma unroll
  for (int kk = 0; kk < 16; kk++) {
    wmma::fragment<wmma::matrix_a, 16, 16, 8, wmma::precision::tf32, wmma::row_major> af;
    wmma::load_matrix_sync(af, arow + (kk << 3), 128);
    #pragma unroll
    for (int nc = 0; nc < 2; nc++) {
      wmma::fragment<wmma::matrix_b, 16, 16, 8, wmma::precision::tf32, wmma::row_major> bf;
      wmma::load_matrix_sync(bf, &Ws[kk << 3][(cg << 5) + (nc << 4)], 68);
      wmma::mma_sync(acc[nc], af, bf, acc[nc]);
    }
  }

  if (rowBase + 64 <= n) {
    #pragma unroll
    for (int nc = 0; nc < 2; nc++) {
      int k = (cg << 1) | nc;
      wmma::store_matrix_sync(&y[(k * n + rowBase + (rg << 4)) * 16], acc[nc], 16,
                              wmma::mem_row_major);
    }
  } else {
    __syncthreads();
    float* stg = (float*)Ws;
    wmma::store_matrix_sync(&stg[(rg << 4) * 68 + (cg << 5)], acc[0], 68, wmma::mem_row_major);
    wmma::store_matrix_sync(&stg[(rg << 4) * 68 + (cg << 5) + 16], acc[1], 68, wmma::mem_row_major);
    __syncthreads();
    int r = tid >> 2;
    int ks = tid & 3;
    int row = rowBase + r;
    if (row < n) {
      float* src = &stg[r * 68 + (ks << 4)];
      float* dst = &y[(ks * n + row) * 16];
      #pragma unroll
      for (int c4 = 0; c4 < 4; c4++) *(float4*)&dst[c4 << 2] = *(float4*)&src[c4 << 2];
    }
  }
}

// ---------------- GEMM2: out[n][64] = sum_k G[k][n][:] @ W2[k] + b2 ----------------
__global__ __launch_bounds__(256) void k_gemm2(
    const float* __restrict__ G, const float* __restrict__ W2,
    const float* __restrict__ b2, float* __restrict__ out, int n) {
  __shared__ float Ws[64][64];
  __shared__ float Gs[64][36];
  int tid = threadIdx.x;
  int rowBase = blockIdx.x * 64;
  for (int s = tid; s < 4096; s += 256) ((float*)Ws)[s] = W2[s];
  float4 acc[4];
  #pragma unroll
  for (int i = 0; i < 4; i++) acc[i] = make_float4(0.f, 0.f, 0.f, 0.f);
  int cg = tid & 15, rg = tid >> 4;
  for (int ch = 0; ch < 2; ch++) {
    __syncthreads();
    #pragma unroll
    for (int s0 = 0; s0 < 2; s0++) {
      int s = s0 * 256 + tid;
      int kk = s >> 8, rem = s & 255;
      int r = rem >> 2, f4 = rem & 3;
      int row = rowBase + r;
      float4 vv = make_float4(0.f, 0.f, 0.f, 0.f);
      if (row < n) vv = *(const float4*)&G[(((ch << 1) | kk) * n + row) * 16 + (f4 << 2)];
      *(float4*)&Gs[r][(kk << 4) | (f4 << 2)] = vv;
    }
    __syncthreads();
    #pragma unroll
    for (int dq = 0; dq < 8; dq++) {
      int d0 = (ch << 5) + (dq << 2);
      float4 w0 = *(const float4*)&Ws[d0 + 0][cg << 2];
      float4 w1 = *(const float4*)&Ws[d0 + 1][cg << 2];
      float4 w2 = *(const float4*)&Ws[d0 + 2][cg << 2];
      float4 w3 = *(const float4*)&Ws[d0 + 3][cg << 2];
      #pragma unroll
      for (int i = 0; i < 4; i++) {
        float4 gv = *(const float4*)&Gs[(rg << 2) + i][dq << 2];
        acc[i].x += gv.x * w0.x + gv.y * w1.x + gv.z * w2.x + gv.w * w3.x;
        acc[i].y += gv.x * w0.y + gv.y * w1.y + gv.z * w2.y + gv.w * w3.y;
        acc[i].z += gv.x * w0.z + gv.y * w1.z + gv.z * w2.z + gv.w * w3.z;
        acc[i].w += gv.x * w0.w + gv.y * w1.w + gv.z * w2.w + gv.w * w3.w;
      }
    }
  }
  float4 bb = *(const float4*)&b2[cg << 2];
  #pragma unroll
  for (int i = 0; i < 4; i++) {
    int r = rowBase + (rg << 2) + i;
    if (r < n) {
      *(float4*)&out[r * 64 + (cg << 2)] = make_float4(
          acc[i].x + bb.x, acc[i].y + bb.y, acc[i].z + bb.z, acc[i].w + bb.w);
    }
  }
}

// ---------------- launch ----------------
extern "C" void kernel_launch(void* const* d_in, const int* in_sizes, int n_in,
                              void* d_out, int out_size) {
  (void)n_in; (void)out_size;
  const float* x  = (const float*)d_in[0];
  const int*   ei = (const int*)d_in[1];
  const float* W1 = (const float*)d_in[2];
  const float* b1 = (const float*)d_in[3];
  const float* W2 = (const float*)d_in[4];
  const float* b2 = (const float*)d_in[5];
  float* out = (float*)d_out;
  int n = in_sizes[0] / 128;
  int E = in_sizes[1] / 2;

  int *cnt, *rp, *base;
  float *dinv, *Wt, *xs, *y, *t, *u, *G;
  float2* csr;
  cudaGetSymbolAddress((void**)&cnt,  g_cnt);
  cudaGetSymbolAddress((void**)&rp,   g_rp);
  cudaGetSymbolAddress((void**)&base, g_base);
  cudaGetSymbolAddress((void**)&dinv, g_dinv);
  cudaGetSymbolAddress((void**)&Wt,   g_Wt);
  cudaGetSymbolAddress((void**)&xs,   g_xs);
  cudaGetSymbolAddress((void**)&csr,  g_csr);
  cudaGetSymbolAddress((void**)&y,    g_y);
  cudaGetSymbolAddress((void**)&t,    g_t);
  cudaGetSymbolAddress((void**)&u,    g_u);
  cudaGetSymbolAddress((void**)&G,    g_G);

  const int TB = 256;
  int gN  = (n + TB - 1) / TB;
  int gE2 = (E / 2 + TB - 1) / TB;
  int gR4 = (n * 4 + TB - 1) / TB;
  int gW  = (n * 32 + TB - 1) / TB;
  int gG  = (n + 63) / 64;
  int nb  = (n + 1023) / 1024;

  k_prepW<<<1, 256>>>(W1, Wt);                    // #1
  k_prepX<<<gW, TB>>>(x, xs, n);                  // #2
  k_zero1<<<gN, TB>>>(cnt, base, n);              // #3
  k_gemm1<<<gG, 256>>>(xs, Wt, y, n);             // #4 -> profiled (WMMA v4)
  k_hist<<<gE2, TB>>>(ei, cnt, E);                // #5
  k_scan1<<<nb, 1024>>>(cnt, rp, base, dinv, n);  // #6
  k_fill<<<gE2, TB>>>(ei, dinv, rp, csr, E);      // #7

  // layer-1 Horner: G0 = relu(y0 + A(y1 + A(y2 + A*y3)) + b1)
  k_spmm<<<gR4, TB>>>(rp, cnt, csr, (const float4*)(y + 3 * n * 16),
                      (const float4*)(y + 2 * n * 16), nullptr, (float4*)t, n);
  k_spmm<<<gR4, TB>>>(rp, cnt, csr, (const float4*)t,
                      (const float4*)(y + 1 * n * 16), nullptr, (float4*)u, n);
  k_spmm<<<gR4, TB>>>(rp, cnt, csr, (const float4*)u,
                      (const float4*)y, b1, (float4*)G, n);

  // layer-2 hops: G[k+1] = A * G[k]
  for (int k = 0; k < 3; k++) {
    k_spmm<<<gR4, TB>>>(rp, cnt, csr, (const float4*)(G + k * n * 16),
                        nullptr, nullptr, (float4*)(G + (k + 1) * n * 16), n);
  }

  // combine + bias
  k_gemm2<<<gG, 256>>>(G, W2, b2, out, n);
}

// round 14
// speedup vs baseline: 1.0840x; 1.0840x over previous
#include <cuda_runtime.h>
#include <mma.h>
#include <math.h>

using namespace nvcuda;

#define NMAX 50000
#define EMAX 800000

// ---------------- scratch (no allocation allowed) ----------------
__device__ __align__(16) int   g_cnt[NMAX];        // in-degree (true counts)
__device__ __align__(16) int   g_rp[NMAX];         // CSR row ptr; fill advances it to row END
__device__ int                 g_base;             // global slot counter (even-padded)
__device__ __align__(16) float g_dinv[NMAX];
__device__ __align__(16) float g_invrs[NMAX];
__device__ __align__(16) float g_Wt[128 * 64];     // tf32, transformed W1
__device__ __align__(16) float2 g_csr[EMAX + NMAX]; // (src bits, weight); rows even-aligned
__device__ __align__(16) float g_y[4 * NMAX * 16]; // layer-1 projections y_k
__device__ __align__(16) float g_t[NMAX * 16];
__device__ __align__(16) float g_u[NMAX * 16];
__device__ __align__(16) float g_G[4 * NMAX * 16]; // layer-2 hops

// ---------------- CSR build ----------------
__global__ void k_zero1(int* __restrict__ a, int* __restrict__ base, int n) {
  int i = blockIdx.x * blockDim.x + threadIdx.x;
  if (i < n) a[i] = 0;
  if (i == 0) *base = 0;
}

__global__ void k_hist(const int* __restrict__ ei, int* __restrict__ cnt, int E) {
  int e = (blockIdx.x * blockDim.x + threadIdx.x) * 2;
  if (e >= E) return;
  atomicAdd(&cnt[ei[E + e]], 1);
  if (e + 1 < E) atomicAdd(&cnt[ei[E + e + 1]], 1);
}

// warp per row: inv_rowsum = 1 / max(sum(x_row), 1e-8)
__global__ void k_invrs(const float* __restrict__ x, float* __restrict__ invrs, int n) {
  int w = (blockIdx.x * blockDim.x + threadIdx.x) >> 5;
  int lane = threadIdx.x & 31;
  if (w >= n) return;
  const float4* x4 = (const float4*)x;
  float4 v = x4[w * 32 + lane];
  float s = v.x + v.y + v.z + v.w;
  #pragma unroll
  for (int o = 16; o; o >>= 1) s += __shfl_xor_sync(0xffffffffu, s, o);
  if (lane == 0) invrs[w] = 1.0f / fmaxf(s, 1e-8f);
}

// one-time W1 transform: Wt[d*64 + k*16+f] = tf32(W1[(k*128+d)*16+f])
__global__ void k_prepW(const float* __restrict__ W1, float* __restrict__ Wt) {
  int tid = threadIdx.x;
  for (int s = tid; s < 8192; s += 256) {
    int d = s >> 6, c = s & 63;
    Wt[s] = wmma::__float_to_tf32(W1[(((c >> 4) << 7) | d) * 16 + (c & 15)]);
  }
}

// per-1024-block exclusive scan over EVEN-PADDED lengths (warp shuffles) +
// atomic block base -> FINAL rp. Every row's slot range starts even -> csr
// pair loads are 16B-aligned. Also emits dinv.
__global__ __launch_bounds__(1024) void k_scan1(const int* __restrict__ cnt,
                                                int* __restrict__ rp,
                                                int* __restrict__ base,
                                                float* __restrict__ dinv, int n) {
  __shared__ int ws[32];
  __shared__ int blockBase;
  int t = threadIdx.x;
  int i = blockIdx.x * 1024 + t;
  int c = (i < n) ? cnt[i] : 0;
  if (i < n) dinv[i] = (c > 0) ? rsqrtf((float)c) : 0.f;
  int cp = (c + 1) & ~1;          // even-padded allocation
  int s = cp;
  #pragma unroll
  for (int o = 1; o < 32; o <<= 1) {
    int p = __shfl_up_sync(0xffffffffu, s, o);
    if ((t & 31) >= o) s += p;
  }
  if ((t & 31) == 31) ws[t >> 5] = s;
  __syncthreads();
  if (t < 32) {
    int b = ws[t];
    int sb = b;
    #pragma unroll
    for (int o = 1; o < 32; o <<= 1) {
      int p = __shfl_up_sync(0xffffffffu, sb, o);
      if (t >= o) sb += p;
    }
    ws[t] = sb - b;
    if (t == 31) blockBase = atomicAdd(base, sb);
  }
  __syncthreads();
  if (i < n) rp[i] = blockBase + (s - cp) + ws[t >> 5];
}

// fill CSR entries: (src, dinv[src]*dinv[dst]) into dst buckets. 2 edges/thread.
__global__ void k_fill(const int* __restrict__ ei, const float* __restrict__ dinv,
                       int* __restrict__ rp, float2* __restrict__ csr, int E) {
  int e = (blockIdx.x * blockDim.x + threadIdx.x) * 2;
  if (e >= E) return;
  int s0 = ei[e];
  int d0 = ei[E + e];
  float w0 = dinv[s0] * dinv[d0];
  int p0 = atomicAdd(&rp[d0], 1);
  if (e + 1 < E) {
    int s1 = ei[e + 1];
    int d1 = ei[E + e + 1];
    float w1 = dinv[s1] * dinv[d1];
    int p1 = atomicAdd(&rp[d1], 1);
    csr[p0] = make_float2(__int_as_float(s0), w0);
    csr[p1] = make_float2(__int_as_float(s1), w1);
  } else {
    csr[p0] = make_float2(__int_as_float(s0), w0);
  }
}

// ---------------- gather SpMM: out[r] = epi(init[r] + sum_e w_e * in[src_e]) ----------------
// rp[r] is the row END (post-fill); start = rp[r] - cnt[r] (EVEN by construction).
// 4 threads per row; csr loaded as aligned float4 PAIRS (half the csr load instrs).
__global__ __launch_bounds__(256) void k_spmm(
    const int* __restrict__ rp, const int* __restrict__ cnt,
    const float2* __restrict__ csr, const float4* __restrict__ in,
    const float4* __restrict__ init, const float* __restrict__ bias,
    float4* __restrict__ out, int n) {
  int idx = blockIdx.x * blockDim.x + threadIdx.x;
  int r = idx >> 2;
  if (r >= n) return;
  int q = idx & 3;
  int len = __ldg(&cnt[r]);
  int start = __ldg(&rp[r]) - len;   // even
  const float4* csr4 = (const float4*)csr;
  int half = start >> 1;
  float4 a0 = make_float4(0.f, 0.f, 0.f, 0.f);
  float4 a1 = make_float4(0.f, 0.f, 0.f, 0.f);
  if (init) a0 = init[(r << 2) + q];
  int i = 0;
  for (; i + 8 <= len; i += 8) {
    int hb = half + (i >> 1);
    float4 p0 = __ldg(&csr4[hb + 0]);   // edges i+0, i+1
    float4 p1 = __ldg(&csr4[hb + 1]);   // edges i+2, i+3
    float4 p2 = __ldg(&csr4[hb + 2]);   // edges i+4, i+5
    float4 p3 = __ldg(&csr4[hb + 3]);   // edges i+6, i+7
    float4 v0 = __ldg(&in[(__float_as_int(p0.x) << 2) + q]);
    float4 v1 = __ldg(&in[(__float_as_int(p0.z) << 2) + q]);
    float4 v2 = __ldg(&in[(__float_as_int(p1.x) << 2) + q]);
    float4 v3 = __ldg(&in[(__float_as_int(p1.z) << 2) + q]);
    float4 v4 = __ldg(&in[(__float_as_int(p2.x) << 2) + q]);
    float4 v5 = __ldg(&in[(__float_as_int(p2.z) << 2) + q]);
    float4 v6 = __ldg(&in[(__float_as_int(p3.x) << 2) + q]);
    float4 v7 = __ldg(&in[(__float_as_int(p3.z) << 2) + q]);
    a0.x += p0.y * v0.x; a0.y += p0.y * v0.y; a0.z += p0.y * v0.z; a0.w += p0.y * v0.w;
    a1.x += p0.w * v1.x; a1.y += p0.w * v1.y; a1.z += p0.w * v1.z; a1.w += p0.w * v1.w;
    a0.x += p1.y * v2.x; a0.y += p1.y * v2.y; a0.z += p1.y * v2.z; a0.w += p1.y * v2.w;
    a1.x += p1.w * v3.x; a1.y += p1.w * v3.y; a1.z += p1.w * v3.z; a1.w += p1.w * v3.w;
    a0.x += p2.y * v4.x; a0.y += p2.y * v4.y; a0.z += p2.y * v4.z; a0.w += p2.y * v4.w;
    a1.x += p2.w * v5.x; a1.y += p2.w * v5.y; a1.z += p2.w * v5.z; a1.w += p2.w * v5.w;
    a0.x += p3.y * v6.x; a0.y += p3.y * v6.y; a0.z += p3.y * v6.z; a0.w += p3.y * v6.w;
    a1.x += p3.w * v7.x; a1.y += p3.w * v7.y; a1.z += p3.w * v7.z; a1.w += p3.w * v7.w;
  }
  for (; i + 2 <= len; i += 2) {
    float4 p0 = __ldg(&csr4[half + (i >> 1)]);
    float4 v0 = __ldg(&in[(__float_as_int(p0.x) << 2) + q]);
    float4 v1 = __ldg(&in[(__float_as_int(p0.z) << 2) + q]);
    a0.x += p0.y * v0.x; a0.y += p0.y * v0.y; a0.z += p0.y * v0.z; a0.w += p0.y * v0.w;
    a1.x += p0.w * v1.x; a1.y += p0.w * v1.y; a1.z += p0.w * v1.z; a1.w += p0.w * v1.w;
  }
  if (i < len) {
    float2 e0 = __ldg(&csr[start + i]);
    float4 v0 = __ldg(&in[(__float_as_int(e0.x) << 2) + q]);
    a0.x += e0.y * v0.x; a0.y += e0.y * v0.y; a0.z += e0.y * v0.z; a0.w += e0.y * v0.w;
  }
  float4 acc = make_float4(a0.x + a1.x, a0.y + a1.y, a0.z + a1.z, a0.w + a1.w);
  if (bias) {
    float4 bb = ((const float4*)bias)[q];
    acc = make_float4(fmaxf(acc.x + bb.x, 0.f), fmaxf(acc.y + bb.y, 0.f),
                      fmaxf(acc.z + bb.z, 0.f), fmaxf(acc.w + bb.w, 0.f));
  }
  out[(r << 2) + q] = acc;
}

// ---------------- GEMM1 (tf32 WMMA v3): y[k][n][16] = (x*invrs) @ W1[k] ----------------
__global__ __launch_bounds__(256) void k_gemm1(
    const float* __restrict__ x, const float* __restrict__ Wt,
    const float* __restrict__ invrs, float* __restrict__ y, int n) {
  __shared__ float Ws[128][68];   // tf32 W, padded stride
  __shared__ float Xs[64][36];    // rows x 32-wide K chunk, scaled + tf32, padded
  int tid = threadIdx.x;
  int wid = tid >> 5;
  int rg = wid >> 1;
  int cg = wid & 1;
  int rowBase = blockIdx.x * 64;

  const float4* Wt4 = (const float4*)Wt;
  for (int s = tid; s < 2048; s += 256) {
    int d = s >> 4, c4 = s & 15;
    *(float4*)&Ws[d][c4 << 2] = Wt4[s];
  }

  wmma::fragment<wmma::accumulator, 16, 16, 8, float> acc[2];
  wmma::fill_fragment(acc[0], 0.0f);
  wmma::fill_fragment(acc[1], 0.0f);

  const float4* x4 = (const float4*)x;
  for (int ch = 0; ch < 4; ch++) {
    __syncthreads();
    for (int s = tid; s < 512; s += 256) {
      int r = s >> 3, d4 = s & 7;
      int row = rowBase + r;
      float4 vv = make_float4(0.f, 0.f, 0.f, 0.f);
      float sc = 0.f;
      if (row < n) {
        vv = x4[row * 32 + (ch << 3) + d4];
        sc = __ldg(&invrs[row]);
      }
      float* dst = &Xs[r][d4 << 2];
      dst[0] = wmma::__float_to_tf32(vv.x * sc);
      dst[1] = wmma::__float_to_tf32(vv.y * sc);
      dst[2] = wmma::__float_to_tf32(vv.z * sc);
      dst[3] = wmma::__float_to_tf32(vv.w * sc);
    }
    __syncthreads();
    #pragma unroll
    for (int kk = 0; kk < 4; kk++) {
      wmma::fragment<wmma::matrix_a, 16, 16, 8, wmma::precision::tf32, wmma::row_major> af;
      wmma::load_matrix_sync(af, &Xs[rg << 4][kk << 3], 36);
      #pragma unroll
      for (int nc = 0; nc < 2; nc++) {
        wmma::fragment<wmma::matrix_b, 16, 16, 8, wmma::precision::tf32, wmma::row_major> bf;
        wmma::load_matrix_sync(bf, &Ws[(ch << 5) + (kk << 3)][(cg << 5) + (nc << 4)], 68);
        wmma::mma_sync(acc[nc], af, bf, acc[nc]);
      }
    }
  }

  if (rowBase + 64 <= n) {
    #pragma unroll
    for (int nc = 0; nc < 2; nc++) {
      int k = (cg << 1) | nc;
      wmma::store_matrix_sync(&y[(k * n + rowBase + (rg << 4)) * 16], acc[nc], 16,
                              wmma::mem_row_major);
    }
  } else {
    __syncthreads();
    float* stg = (float*)Ws;
    wmma::store_matrix_sync(&stg[(rg << 4) * 68 + (cg << 5)], acc[0], 68, wmma::mem_row_major);
    wmma::store_matrix_sync(&stg[(rg << 4) * 68 + (cg << 5) + 16], acc[1], 68, wmma::mem_row_major);
    __syncthreads();
    int r = tid >> 2;
    int ks = tid & 3;
    int row = rowBase + r;
    if (row < n) {
      float* src = &stg[r * 68 + (ks << 4)];
      float* dst = &y[(ks * n + row) * 16];
      #pragma unroll
      for (int c4 = 0; c4 < 4; c4++) *(float4*)&dst[c4 << 2] = *(float4*)&src[c4 << 2];
    }
  }
}

// ---------------- GEMM2: out[n][64] = sum_k G[k][n][:] @ W2[k] + b2 ----------------
__global__ __launch_bounds__(256) void k_gemm2(
    const float* __restrict__ G, const float* __restrict__ W2,
    const float* __restrict__ b2, float* __restrict__ out, int n) {
  __shared__ float Ws[64][64];
  __shared__ float Gs[64][36];
  int tid = threadIdx.x;
  int rowBase = blockIdx.x * 64;
  for (int s = tid; s < 4096; s += 256) ((float*)Ws)[s] = W2[s];
  float4 acc[4];
  #pragma unroll
  for (int i = 0; i < 4; i++) acc[i] = make_float4(0.f, 0.f, 0.f, 0.f);
  int cg = tid & 15, rg = tid >> 4;
  for (int ch = 0; ch < 2; ch++) {
    __syncthreads();
    #pragma unroll
    for (int s0 = 0; s0 < 2; s0++) {
      int s = s0 * 256 + tid;
      int kk = s >> 8, rem = s & 255;
      int r = rem >> 2, f4 = rem & 3;
      int row = rowBase + r;
      float4 vv = make_float4(0.f, 0.f, 0.f, 0.f);
      if (row < n) vv = *(const float4*)&G[(((ch << 1) | kk) * n + row) * 16 + (f4 << 2)];
      *(float4*)&Gs[r][(kk << 4) | (f4 << 2)] = vv;
    }
    __syncthreads();
    #pragma unroll
    for (int dq = 0; dq < 8; dq++) {
      int d0 = (ch << 5) + (dq << 2);
      float4 w0 = *(const float4*)&Ws[d0 + 0][cg << 2];
      float4 w1 = *(const float4*)&Ws[d0 + 1][cg << 2];
      float4 w2 = *(const float4*)&Ws[d0 + 2][cg << 2];
      float4 w3 = *(const float4*)&Ws[d0 + 3][cg << 2];
      #pragma unroll
      for (int i = 0; i < 4; i++) {
        float4 gv = *(const float4*)&Gs[(rg << 2) + i][dq << 2];
        acc[i].x += gv.x * w0.x + gv.y * w1.x + gv.z * w2.x + gv.w * w3.x;
        acc[i].y += gv.x * w0.y + gv.y * w1.y + gv.z * w2.y + gv.w * w3.y;
        acc[i].z += gv.x * w0.z + gv.y * w1.z + gv.z * w2.z + gv.w * w3.z;
        acc[i].w += gv.x * w0.w + gv.y * w1.w + gv.z * w2.w + gv.w * w3.w;
      }
    }
  }
  float4 bb = *(const float4*)&b2[cg << 2];
  #pragma unroll
  for (int i = 0; i < 4; i++) {
    int r = rowBase + (rg << 2) + i;
    if (r < n) {
      *(float4*)&out[r * 64 + (cg << 2)] = make_float4(
          acc[i].x + bb.x, acc[i].y + bb.y, acc[i].z + bb.z, acc[i].w + bb.w);
    }
  }
}

// ---------------- launch ----------------
extern "C" void kernel_launch(void* const* d_in, const int* in_sizes, int n_in,
                              void* d_out, int out_size) {
  (void)n_in; (void)out_size;
  const float* x  = (const float*)d_in[0];
  const int*   ei = (const int*)d_in[1];
  const float* W1 = (const float*)d_in[2];
  const float* b1 = (const float*)d_in[3];
  const float* W2 = (const float*)d_in[4];
  const float* b2 = (const float*)d_in[5];
  float* out = (float*)d_out;
  int n = in_sizes[0] / 128;
  int E = in_sizes[1] / 2;

  int *cnt, *rp, *base;
  float *dinv, *invrs, *Wt, *y, *t, *u, *G;
  float2* csr;
  cudaGetSymbolAddress((void**)&cnt,   g_cnt);
  cudaGetSymbolAddress((void**)&rp,    g_rp);
  cudaGetSymbolAddress((void**)&base,  g_base);
  cudaGetSymbolAddress((void**)&dinv,  g_dinv);
  cudaGetSymbolAddress((void**)&invrs, g_invrs);
  cudaGetSymbolAddress((void**)&Wt,    g_Wt);
  cudaGetSymbolAddress((void**)&csr,   g_csr);
  cudaGetSymbolAddress((void**)&y,     g_y);
  cudaGetSymbolAddress((void**)&t,     g_t);
  cudaGetSymbolAddress((void**)&u,     g_u);
  cudaGetSymbolAddress((void**)&G,     g_G);

  const int TB = 256;
  int gN  = (n + TB - 1) / TB;
  int gE2 = (E / 2 + TB - 1) / TB;
  int gR4 = (n * 4 + TB - 1) / TB;
  int gW  = (n * 32 + TB - 1) / TB;
  int gG  = (n + 63) / 64;
  int nb  = (n + 1023) / 1024;

  // CSR build (serial)
  k_zero1<<<gN, TB>>>(cnt, base, n);              // #1
  k_hist<<<gE2, TB>>>(ei, cnt, E);                // #2
  k_scan1<<<nb, 1024>>>(cnt, rp, base, dinv, n);  // #3
  k_fill<<<gE2, TB>>>(ei, dinv, rp, csr, E);      // #4 -> profiled
  k_prepW<<<1, 256>>>(W1, Wt);                    // #5
  k_invrs<<<gW, TB>>>(x, invrs, n);               // #6
  k_gemm1<<<gG, 256>>>(x, Wt, invrs, y, n);       // #7

  // layer-1 Horner: G0 = relu(y0 + A(y1 + A(y2 + A*y3)) + b1)
  k_spmm<<<gR4, TB>>>(rp, cnt, csr, (const float4*)(y + 3 * n * 16),
                      (const float4*)(y + 2 * n * 16), nullptr, (float4*)t, n);
  k_spmm<<<gR4, TB>>>(rp, cnt, csr, (const float4*)t,
                      (const float4*)(y + 1 * n * 16), nullptr, (float4*)u, n);
  k_spmm<<<gR4, TB>>>(rp, cnt, csr, (const float4*)u,
                      (const float4*)y, b1, (float4*)G, n);

  // layer-2 hops: G[k+1] = A * G[k]
  for (int k = 0; k < 3; k++) {
    k_spmm<<<gR4, TB>>>(rp, cnt, csr, (const float4*)(G + k * n * 16),
                        nullptr, nullptr, (float4*)(G + (k + 1) * n * 16), n);
  }

  // combine + bias
  k_gemm2<<<gG, 256>>>(G, W2, b2, out, n);
}

// round 15
// speedup vs baseline: 1.1328x; 1.0450x over previous
#include <cuda_runtime.h>
#include <mma.h>
#include <math.h>

using namespace nvcuda;

#define NMAX 50000
#define EMAX 800000
#define SEG_CAP 2560   // max edges staged per 64-row block (mean ~1024, 48 sigma)

// ---------------- scratch (no allocation allowed) ----------------
__device__ __align__(16) int   g_cnt[NMAX];        // in-degree (true counts); re-zeroed by gemm2
__device__ __align__(16) int   g_rp[NMAX];         // CSR row ptr; fill advances it to row END
__device__ int                 g_base;             // global slot counter; re-zeroed by gemm2
__device__ __align__(16) float g_dinv[NMAX];
__device__ __align__(16) float g_invrs[NMAX];
__device__ __align__(16) float g_Wt[128 * 64];     // tf32, transformed W1
__device__ __align__(16) float2 g_csr[EMAX + NMAX]; // (src bits, weight); rows even-aligned
__device__ __align__(16) float g_y[4 * NMAX * 16]; // layer-1 projections y_k
__device__ __align__(16) float g_t[NMAX * 16];
__device__ __align__(16) float g_u[NMAX * 16];
__device__ __align__(16) float g_G[4 * NMAX * 16]; // layer-2 hops

// ---------------- CSR build ----------------
__global__ void k_hist(const int* __restrict__ ei, int* __restrict__ cnt, int E) {
  int e = (blockIdx.x * blockDim.x + threadIdx.x) * 2;
  if (e >= E) return;
  atomicAdd(&cnt[ei[E + e]], 1);
  if (e + 1 < E) atomicAdd(&cnt[ei[E + e + 1]], 1);
}

// warp per row: inv_rowsum = 1 / max(sum(x_row), 1e-8)
__global__ void k_invrs(const float* __restrict__ x, float* __restrict__ invrs, int n) {
  int w = (blockIdx.x * blockDim.x + threadIdx.x) >> 5;
  int lane = threadIdx.x & 31;
  if (w >= n) return;
  const float4* x4 = (const float4*)x;
  float4 v = x4[w * 32 + lane];
  float s = v.x + v.y + v.z + v.w;
  #pragma unroll
  for (int o = 16; o; o >>= 1) s += __shfl_xor_sync(0xffffffffu, s, o);
  if (lane == 0) invrs[w] = 1.0f / fmaxf(s, 1e-8f);
}

// one-time W1 transform: Wt[d*64 + k*16+f] = tf32(W1[(k*128+d)*16+f])
__global__ void k_prepW(const float* __restrict__ W1, float* __restrict__ Wt) {
  int tid = threadIdx.x;
  for (int s = tid; s < 8192; s += 256) {
    int d = s >> 6, c = s & 63;
    Wt[s] = wmma::__float_to_tf32(W1[(((c >> 4) << 7) | d) * 16 + (c & 15)]);
  }
}

// per-1024-block exclusive scan over EVEN-PADDED lengths + atomic block base.
// Every row's slot range starts even -> csr pair loads 16B-aligned. Emits dinv.
__global__ __launch_bounds__(1024) void k_scan1(const int* __restrict__ cnt,
                                                int* __restrict__ rp,
                                                int* __restrict__ base,
                                                float* __restrict__ dinv, int n) {
  __shared__ int ws[32];
  __shared__ int blockBase;
  int t = threadIdx.x;
  int i = blockIdx.x * 1024 + t;
  int c = (i < n) ? cnt[i] : 0;
  if (i < n) dinv[i] = (c > 0) ? rsqrtf((float)c) : 0.f;
  int cp = (c + 1) & ~1;          // even-padded allocation
  int s = cp;
  #pragma unroll
  for (int o = 1; o < 32; o <<= 1) {
    int p = __shfl_up_sync(0xffffffffu, s, o);
    if ((t & 31) >= o) s += p;
  }
  if ((t & 31) == 31) ws[t >> 5] = s;
  __syncthreads();
  if (t < 32) {
    int b = ws[t];
    int sb = b;
    #pragma unroll
    for (int o = 1; o < 32; o <<= 1) {
      int p = __shfl_up_sync(0xffffffffu, sb, o);
      if (t >= o) sb += p;
    }
    ws[t] = sb - b;
    if (t == 31) blockBase = atomicAdd(base, sb);
  }
  __syncthreads();
  if (i < n) rp[i] = blockBase + (s - cp) + ws[t >> 5];
}

// fill CSR entries: (src, dinv[src]*dinv[dst]) into dst buckets. 2 edges/thread.
__global__ void k_fill(const int* __restrict__ ei, const float* __restrict__ dinv,
                       int* __restrict__ rp, float2* __restrict__ csr, int E) {
  int e = (blockIdx.x * blockDim.x + threadIdx.x) * 2;
  if (e >= E) return;
  int s0 = ei[e];
  int d0 = ei[E + e];
  float w0 = dinv[s0] * dinv[d0];
  int p0 = atomicAdd(&rp[d0], 1);
  if (e + 1 < E) {
    int s1 = ei[e + 1];
    int d1 = ei[E + e + 1];
    float w1 = dinv[s1] * dinv[d1];
    int p1 = atomicAdd(&rp[d1], 1);
    csr[p0] = make_float2(__int_as_float(s0), w0);
    csr[p1] = make_float2(__int_as_float(s1), w1);
  } else {
    csr[p0] = make_float2(__int_as_float(s0), w0);
  }
}

// ---------------- gather SpMM v5 (smem-staged CSR) ----------------
// Block = 64 rows; its rows occupy ONE contiguous ascending csr segment
// (64-row blocks nest inside 1024-row scan blocks). Stage segment into smem
// once (coalesced), quads then read entries via smem broadcast. Fallback to
// direct gmem loads if a segment exceeds SEG_CAP (uniform per block).
__global__ __launch_bounds__(256) void k_spmm(
    const int* __restrict__ rp, const int* __restrict__ cnt,
    const float2* __restrict__ csr, const float4* __restrict__ in,
    const float4* __restrict__ init, const float* __restrict__ bias,
    float4* __restrict__ out, int n) {
  __shared__ float4 se[SEG_CAP / 2];   // 20KB: SEG_CAP edges as float4 pairs
  int tid = threadIdx.x;
  int r0 = blockIdx.x * 64;
  int rLast = min(r0 + 63, n - 1);
  int segStart = __ldg(&rp[r0]) - __ldg(&cnt[r0]);   // even
  int segEnd = __ldg(&rp[rLast]);
  int segLen = segEnd - segStart;
  bool useSmem = (segLen <= SEG_CAP);
  if (useSmem) {
    const float4* g4 = (const float4*)csr + (segStart >> 1);
    int nf4 = (segLen + 1) >> 1;
    for (int s = tid; s < nf4; s += 256) se[s] = __ldg(&g4[s]);
    __syncthreads();
  }
  int r = r0 + (tid >> 2);
  if (r >= n) return;
  int q = tid & 3;
  int len = __ldg(&cnt[r]);
  int start = __ldg(&rp[r]) - len;   // even
  float4 a0 = make_float4(0.f, 0.f, 0.f, 0.f);
  float4 a1 = make_float4(0.f, 0.f, 0.f, 0.f);
  if (init) a0 = init[(r << 2) + q];
  int i = 0;
  if (useSmem) {
    const float4* b4 = se + ((start - segStart) >> 1);
    for (; i + 8 <= len; i += 8) {
      int hb = i >> 1;
      float4 p0 = b4[hb + 0];
      float4 p1 = b4[hb + 1];
      float4 p2 = b4[hb + 2];
      float4 p3 = b4[hb + 3];
      float4 v0 = __ldg(&in[(__float_as_int(p0.x) << 2) + q]);
      float4 v1 = __ldg(&in[(__float_as_int(p0.z) << 2) + q]);
      float4 v2 = __ldg(&in[(__float_as_int(p1.x) << 2) + q]);
      float4 v3 = __ldg(&in[(__float_as_int(p1.z) << 2) + q]);
      float4 v4 = __ldg(&in[(__float_as_int(p2.x) << 2) + q]);
      float4 v5 = __ldg(&in[(__float_as_int(p2.z) << 2) + q]);
      float4 v6 = __ldg(&in[(__float_as_int(p3.x) << 2) + q]);
      float4 v7 = __ldg(&in[(__float_as_int(p3.z) << 2) + q]);
      a0.x += p0.y * v0.x; a0.y += p0.y * v0.y; a0.z += p0.y * v0.z; a0.w += p0.y * v0.w;
      a1.x += p0.w * v1.x; a1.y += p0.w * v1.y; a1.z += p0.w * v1.z; a1.w += p0.w * v1.w;
      a0.x += p1.y * v2.x; a0.y += p1.y * v2.y; a0.z += p1.y * v2.z; a0.w += p1.y * v2.w;
      a1.x += p1.w * v3.x; a1.y += p1.w * v3.y; a1.z += p1.w * v3.z; a1.w += p1.w * v3.w;
      a0.x += p2.y * v4.x; a0.y += p2.y * v4.y; a0.z += p2.y * v4.z; a0.w += p2.y * v4.w;
      a1.x += p2.w * v5.x; a1.y += p2.w * v5.y; a1.z += p2.w * v5.z; a1.w += p2.w * v5.w;
      a0.x += p3.y * v6.x; a0.y += p3.y * v6.y; a0.z += p3.y * v6.z; a0.w += p3.y * v6.w;
      a1.x += p3.w * v7.x; a1.y += p3.w * v7.y; a1.z += p3.w * v7.z; a1.w += p3.w * v7.w;
    }
    for (; i + 2 <= len; i += 2) {
      float4 p0 = b4[i >> 1];
      float4 v0 = __ldg(&in[(__float_as_int(p0.x) << 2) + q]);
      float4 v1 = __ldg(&in[(__float_as_int(p0.z) << 2) + q]);
      a0.x += p0.y * v0.x; a0.y += p0.y * v0.y; a0.z += p0.y * v0.z; a0.w += p0.y * v0.w;
      a1.x += p0.w * v1.x; a1.y += p0.w * v1.y; a1.z += p0.w * v1.z; a1.w += p0.w * v1.w;
    }
    if (i < len) {
      float2 e0 = ((const float2*)se)[(start - segStart) + i];
      float4 v0 = __ldg(&in[(__float_as_int(e0.x) << 2) + q]);
      a0.x += e0.y * v0.x; a0.y += e0.y * v0.y; a0.z += e0.y * v0.z; a0.w += e0.y * v0.w;
    }
  } else {
    const float4* csr4 = (const float4*)csr;
    int half = start >> 1;
    for (; i + 8 <= len; i += 8) {
      int hb = half + (i >> 1);
      float4 p0 = __ldg(&csr4[hb + 0]);
      float4 p1 = __ldg(&csr4[hb + 1]);
      float4 p2 = __ldg(&csr4[hb + 2]);
      float4 p3 = __ldg(&csr4[hb + 3]);
      float4 v0 = __ldg(&in[(__float_as_int(p0.x) << 2) + q]);
      float4 v1 = __ldg(&in[(__float_as_int(p0.z) << 2) + q]);
      float4 v2 = __ldg(&in[(__float_as_int(p1.x) << 2) + q]);
      float4 v3 = __ldg(&in[(__float_as_int(p1.z) << 2) + q]);
      float4 v4 = __ldg(&in[(__float_as_int(p2.x) << 2) + q]);
      float4 v5 = __ldg(&in[(__float_as_int(p2.z) << 2) + q]);
      float4 v6 = __ldg(&in[(__float_as_int(p3.x) << 2) + q]);
      float4 v7 = __ldg(&in[(__float_as_int(p3.z) << 2) + q]);
      a0.x += p0.y * v0.x; a0.y += p0.y * v0.y; a0.z += p0.y * v0.z; a0.w += p0.y * v0.w;
      a1.x += p0.w * v1.x; a1.y += p0.w * v1.y; a1.z += p0.w * v1.z; a1.w += p0.w * v1.w;
      a0.x += p1.y * v2.x; a0.y += p1.y * v2.y; a0.z += p1.y * v2.z; a0.w += p1.y * v2.w;
      a1.x += p1.w * v3.x; a1.y += p1.w * v3.y; a1.z += p1.w * v3.z; a1.w += p1.w * v3.w;
      a0.x += p2.y * v4.x; a0.y += p2.y * v4.y; a0.z += p2.y * v4.z; a0.w += p2.y * v4.w;
      a1.x += p2.w * v5.x; a1.y += p2.w * v5.y; a1.z += p2.w * v5.z; a1.w += p2.w * v5.w;
      a0.x += p3.y * v6.x; a0.y += p3.y * v6.y; a0.z += p3.y * v6.z; a0.w += p3.y * v6.w;
      a1.x += p3.w * v7.x; a1.y += p3.w * v7.y; a1.z += p3.w * v7.z; a1.w += p3.w * v7.w;
    }
    for (; i + 2 <= len; i += 2) {
      float4 p0 = __ldg(&csr4[half + (i >> 1)]);
      float4 v0 = __ldg(&in[(__float_as_int(p0.x) << 2) + q]);
      float4 v1 = __ldg(&in[(__float_as_int(p0.z) << 2) + q]);
      a0.x += p0.y * v0.x; a0.y += p0.y * v0.y; a0.z += p0.y * v0.z; a0.w += p0.y * v0.w;
      a1.x += p0.w * v1.x; a1.y += p0.w * v1.y; a1.z += p0.w * v1.z; a1.w += p0.w * v1.w;
    }
    if (i < len) {
      float2 e0 = __ldg(&csr[start + i]);
      float4 v0 = __ldg(&in[(__float_as_int(e0.x) << 2) + q]);
      a0.x += e0.y * v0.x; a0.y += e0.y * v0.y; a0.z += e0.y * v0.z; a0.w += e0.y * v0.w;
    }
  }
  float4 acc = make_float4(a0.x + a1.x, a0.y + a1.y, a0.z + a1.z, a0.w + a1.w);
  if (bias) {
    float4 bb = ((const float4*)bias)[q];
    acc = make_float4(fmaxf(acc.x + bb.x, 0.f), fmaxf(acc.y + bb.y, 0.f),
                      fmaxf(acc.z + bb.z, 0.f), fmaxf(acc.w + bb.w, 0.f));
  }
  out[(r << 2) + q] = acc;
}

// ---------------- GEMM1 (tf32 WMMA v3): y[k][n][16] = (x*invrs) @ W1[k] ----------------
__global__ __launch_bounds__(256) void k_gemm1(
    const float* __restrict__ x, const float* __restrict__ Wt,
    const float* __restrict__ invrs, float* __restrict__ y, int n) {
  __shared__ float Ws[128][68];
  __shared__ float Xs[64][36];
  int tid = threadIdx.x;
  int wid = tid >> 5;
  int rg = wid >> 1;
  int cg = wid & 1;
  int rowBase = blockIdx.x * 64;

  const float4* Wt4 = (const float4*)Wt;
  for (int s = tid; s < 2048; s += 256) {
    int d = s >> 4, c4 = s & 15;
    *(float4*)&Ws[d][c4 << 2] = Wt4[s];
  }

  wmma::fragment<wmma::accumulator, 16, 16, 8, float> acc[2];
  wmma::fill_fragment(acc[0], 0.0f);
  wmma::fill_fragment(acc[1], 0.0f);

  const float4* x4 = (const float4*)x;
  for (int ch = 0; ch < 4; ch++) {
    __syncthreads();
    for (int s = tid; s < 512; s += 256) {
      int r = s >> 3, d4 = s & 7;
      int row = rowBase + r;
      float4 vv = make_float4(0.f, 0.f, 0.f, 0.f);
      float sc = 0.f;
      if (row < n) {
        vv = x4[row * 32 + (ch << 3) + d4];
        sc = __ldg(&invrs[row]);
      }
      float* dst = &Xs[r][d4 << 2];
      dst[0] = wmma::__float_to_tf32(vv.x * sc);
      dst[1] = wmma::__float_to_tf32(vv.y * sc);
      dst[2] = wmma::__float_to_tf32(vv.z * sc);
      dst[3] = wmma::__float_to_tf32(vv.w * sc);
    }
    __syncthreads();
    #pragma unroll
    for (int kk = 0; kk < 4; kk++) {
      wmma::fragment<wmma::matrix_a, 16, 16, 8, wmma::precision::tf32, wmma::row_major> af;
      wmma::load_matrix_sync(af, &Xs[rg << 4][kk << 3], 36);
      #pragma unroll
      for (int nc = 0; nc < 2; nc++) {
        wmma::fragment<wmma::matrix_b, 16, 16, 8, wmma::precision::tf32, wmma::row_major> bf;
        wmma::load_matrix_sync(bf, &Ws[(ch << 5) + (kk << 3)][(cg << 5) + (nc << 4)], 68);
        wmma::mma_sync(acc[nc], af, bf, acc[nc]);
      }
    }
  }

  if (rowBase + 64 <= n) {
    #pragma unroll
    for (int nc = 0; nc < 2; nc++) {
      int k = (cg << 1) | nc;
      wmma::store_matrix_sync(&y[(k * n + rowBase + (rg << 4)) * 16], acc[nc], 16,
                              wmma::mem_row_major);
    }
  } else {
    __syncthreads();
    float* stg = (float*)Ws;
    wmma::store_matrix_sync(&stg[(rg << 4) * 68 + (cg << 5)], acc[0], 68, wmma::mem_row_major);
    wmma::store_matrix_sync(&stg[(rg << 4) * 68 + (cg << 5) + 16], acc[1], 68, wmma::mem_row_major);
    __syncthreads();
    int r = tid >> 2;
    int ks = tid & 3;
    int row = rowBase + r;
    if (row < n) {
      float* src = &stg[r * 68 + (ks << 4)];
      float* dst = &y[(ks * n + row) * 16];
      #pragma unroll
      for (int c4 = 0; c4 < 4; c4++) *(float4*)&dst[c4 << 2] = *(float4*)&src[c4 << 2];
    }
  }
}

// ---------------- GEMM2 + cleanup: out = sum_k G[k] @ W2[k] + b2; re-zero cnt/base ----------------
__global__ __launch_bounds__(256) void k_gemm2(
    const float* __restrict__ G, const float* __restrict__ W2,
    const float* __restrict__ b2, float* __restrict__ out,
    int* __restrict__ cnt, int* __restrict__ base, int n) {
  // cleanup for next graph replay (runs last in the launch sequence)
  {
    int i = blockIdx.x * blockDim.x + threadIdx.x;
    if (i < n) cnt[i] = 0;
    if (i == 0) *base = 0;
  }
  __shared__ float Ws[64][64];
  __shared__ float Gs[64][36];
  int tid = threadIdx.x;
  int rowBase = blockIdx.x * 64;
  for (int s = tid; s < 4096; s += 256) ((float*)Ws)[s] = W2[s];
  float4 acc[4];
  #pragma unroll
  for (int i = 0; i < 4; i++) acc[i] = make_float4(0.f, 0.f, 0.f, 0.f);
  int cg = tid & 15, rg = tid >> 4;
  for (int ch = 0; ch < 2; ch++) {
    __syncthreads();
    #pragma unroll
    for (int s0 = 0; s0 < 2; s0++) {
      int s = s0 * 256 + tid;
      int kk = s >> 8, rem = s & 255;
      int r = rem >> 2, f4 = rem & 3;
      int row = rowBase + r;
      float4 vv = make_float4(0.f, 0.f, 0.f, 0.f);
      if (row < n) vv = *(const float4*)&G[(((ch << 1) | kk) * n + row) * 16 + (f4 << 2)];
      *(float4*)&Gs[r][(kk << 4) | (f4 << 2)] = vv;
    }
    __syncthreads();
    #pragma unroll
    for (int dq = 0; dq < 8; dq++) {
      int d0 = (ch << 5) + (dq << 2);
      float4 w0 = *(const float4*)&Ws[d0 + 0][cg << 2];
      float4 w1 = *(const float4*)&Ws[d0 + 1][cg << 2];
      float4 w2 = *(const float4*)&Ws[d0 + 2][cg << 2];
      float4 w3 = *(const float4*)&Ws[d0 + 3][cg << 2];
      #pragma unroll
      for (int i = 0; i < 4; i++) {
        float4 gv = *(const float4*)&Gs[(rg << 2) + i][dq << 2];
        acc[i].x += gv.x * w0.x + gv.y * w1.x + gv.z * w2.x + gv.w * w3.x;
        acc[i].y += gv.x * w0.y + gv.y * w1.y + gv.z * w2.y + gv.w * w3.y;
        acc[i].z += gv.x * w0.z + gv.y * w1.z + gv.z * w2.z + gv.w * w3.z;
        acc[i].w += gv.x * w0.w + gv.y * w1.w + gv.z * w2.w + gv.w * w3.w;
      }
    }
  }
  float4 bb = *(const float4*)&b2[cg << 2];
  #pragma unroll
  for (int i = 0; i < 4; i++) {
    int r = rowBase + (rg << 2) + i;
    if (r < n) {
      *(float4*)&out[r * 64 + (cg << 2)] = make_float4(
          acc[i].x + bb.x, acc[i].y + bb.y, acc[i].z + bb.z, acc[i].w + bb.w);
    }
  }
}

// ---------------- launch ----------------
extern "C" void kernel_launch(void* const* d_in, const int* in_sizes, int n_in,
                              void* d_out, int out_size) {
  (void)n_in; (void)out_size;
  const float* x  = (const float*)d_in[0];
  const int*   ei = (const int*)d_in[1];
  const float* W1 = (const float*)d_in[2];
  const float* b1 = (const float*)d_in[3];
  const float* W2 = (const float*)d_in[4];
  const float* b2 = (const float*)d_in[5];
  float* out = (float*)d_out;
  int n = in_sizes[0] / 128;
  int E = in_sizes[1] / 2;

  int *cnt, *rp, *base;
  float *dinv, *invrs, *Wt, *y, *t, *u, *G;
  float2* csr;
  cudaGetSymbolAddress((void**)&cnt,   g_cnt);
  cudaGetSymbolAddress((void**)&rp,    g_rp);
  cudaGetSymbolAddress((void**)&base,  g_base);
  cudaGetSymbolAddress((void**)&dinv,  g_dinv);
  cudaGetSymbolAddress((void**)&invrs, g_invrs);
  cudaGetSymbolAddress((void**)&Wt,    g_Wt);
  cudaGetSymbolAddress((void**)&csr,   g_csr);
  cudaGetSymbolAddress((void**)&y,     g_y);
  cudaGetSymbolAddress((void**)&t,     g_t);
  cudaGetSymbolAddress((void**)&u,     g_u);
  cudaGetSymbolAddress((void**)&G,     g_G);

  const int TB = 256;
  int gE2 = (E / 2 + TB - 1) / TB;
  int gR4 = (n * 4 + TB - 1) / TB;   // 64 rows per block (256 thr / 4 per row)
  int gW  = (n * 32 + TB - 1) / TB;
  int gG  = (n + 63) / 64;
  int nb  = (n + 1023) / 1024;

  // CSR build (cnt/base were zeroed by last call's gemm2; zero-init on load)
  k_hist<<<gE2, TB>>>(ei, cnt, E);                // #1
  k_scan1<<<nb, 1024>>>(cnt, rp, base, dinv, n);  // #2
  k_prepW<<<1, 256>>>(W1, Wt);                    // #3
  k_fill<<<gE2, TB>>>(ei, dinv, rp, csr, E);      // #4 -> profiled
  k_invrs<<<gW, TB>>>(x, invrs, n);               // #5
  k_gemm1<<<gG, 256>>>(x, Wt, invrs, y, n);       // #6

  // layer-1 Horner: G0 = relu(y0 + A(y1 + A(y2 + A*y3)) + b1)
  k_spmm<<<gR4, TB>>>(rp, cnt, csr, (const float4*)(y + 3 * n * 16),
                      (const float4*)(y + 2 * n * 16), nullptr, (float4*)t, n);
  k_spmm<<<gR4, TB>>>(rp, cnt, csr, (const float4*)t,
                      (const float4*)(y + 1 * n * 16), nullptr, (float4*)u, n);
  k_spmm<<<gR4, TB>>>(rp, cnt, csr, (const float4*)u,
                      (const float4*)y, b1, (float4*)G, n);

  // layer-2 hops: G[k+1] = A * G[k]
  for (int k = 0; k < 3; k++) {
    k_spmm<<<gR4, TB>>>(rp, cnt, csr, (const float4*)(G + k * n * 16),
                        nullptr, nullptr, (float4*)(G + (k + 1) * n * 16), n);
  }

  // combine + bias + cleanup for next replay
  k_gemm2<<<gG, 256>>>(G, W2, b2, out, cnt, base, n);
}